// round 14
// baseline (speedup 1.0000x reference)
#include <cuda_runtime.h>
#include <cstdint>

#define N_HID     128
#define N_ETYPES  10
#define N_EDGES   100000
#define TOTAL_EDGES (N_ETYPES * N_EDGES)

#define EPS        4                         // edges per stage
#define NSTAGES    (TOTAL_EDGES / EPS)       // 250000
#define NBLOCKS    888
#define NWARPS_B   4
#define TOT_WARPS  (NBLOCKS * NWARPS_B)      // 3552

#define ROW_BYTES  528                       // 512 + 16 pad (bank-phase spread)
#define STAGE_BYTES (8 * ROW_BYTES)          // 4224
#define WARP_SMEM  (2 * STAGE_BYTES)         // 8448
#define BLOCK_SMEM (NWARPS_B * WARP_SMEM)    // 33792 (< 48KB static limit)

__device__ __forceinline__ void cp16(uint32_t dst, const void* src) {
    asm volatile("cp.async.cg.shared.global [%0], [%1], 16;"
                 :: "r"(dst), "l"(src));
}
__device__ __forceinline__ void cp_commit() {
    asm volatile("cp.async.commit_group;" ::: "memory");
}
__device__ __forceinline__ void cp_wait1() {
    asm volatile("cp.async.wait_group 1;" ::: "memory");
}
__device__ __forceinline__ void cp_wait0() {
    asm volatile("cp.async.wait_group 0;" ::: "memory");
}

// Issue 8 warp-wide row copies (4 edges x {src,dst}) into stage buffer.
__device__ __forceinline__ void issue_stage(
    uint32_t stage_smem, const float* __restrict__ h,
    int4 s4, int4 d4, int lane)
{
    const int ls = lane * 16;
    cp16(stage_smem + 0 * ROW_BYTES + ls, (const char*)(h + (size_t)s4.x * N_HID) + ls);
    cp16(stage_smem + 1 * ROW_BYTES + ls, (const char*)(h + (size_t)d4.x * N_HID) + ls);
    cp16(stage_smem + 2 * ROW_BYTES + ls, (const char*)(h + (size_t)s4.y * N_HID) + ls);
    cp16(stage_smem + 3 * ROW_BYTES + ls, (const char*)(h + (size_t)d4.y * N_HID) + ls);
    cp16(stage_smem + 4 * ROW_BYTES + ls, (const char*)(h + (size_t)s4.z * N_HID) + ls);
    cp16(stage_smem + 5 * ROW_BYTES + ls, (const char*)(h + (size_t)d4.z * N_HID) + ls);
    cp16(stage_smem + 6 * ROW_BYTES + ls, (const char*)(h + (size_t)s4.w * N_HID) + ls);
    cp16(stage_smem + 7 * ROW_BYTES + ls, (const char*)(h + (size_t)d4.w * N_HID) + ls);
    cp_commit();
}

__global__ void __launch_bounds__(128) distmult_kernel(
    const float* __restrict__ h,
    const float* __restrict__ W,
    const int* __restrict__ src,
    const int* __restrict__ dst,
    const int* __restrict__ rel,
    float* __restrict__ out)
{
    __shared__ __align__(16) char smem[BLOCK_SMEM];

    const int wib  = threadIdx.x >> 5;
    const int lane = threadIdx.x & 31;
    const int gw   = blockIdx.x * NWARPS_B + wib;

    // contiguous partition of stages across warps
    const int base_cnt = NSTAGES / TOT_WARPS;            // 70
    const int rem      = NSTAGES - base_cnt * TOT_WARPS; // 1360
    const int start = gw * base_cnt + (gw < rem ? gw : rem);
    const int cnt   = base_cnt + (gw < rem ? 1 : 0);

    uint32_t wbase;
    {
        const char* p = smem + wib * WARP_SMEM;
        asm("{ .reg .u64 t; cvta.to.shared.u64 t, %1; cvt.u32.u64 %0, t; }"
            : "=r"(wbase) : "l"(p));
    }

    const int j = lane & 7;        // 16B slice within a 128B chunk
    const int o = lane >> 3;       // edge within stage

    // ---- prolog: fill both stage buffers ----
    int4 sI0 = __ldg((const int4*)(src + (size_t)(start + 0) * EPS));
    int4 dI0 = __ldg((const int4*)(dst + (size_t)(start + 0) * EPS));
    issue_stage(wbase, h, sI0, dI0, lane);
    int4 sI1 = __ldg((const int4*)(src + (size_t)(start + 1) * EPS));
    int4 dI1 = __ldg((const int4*)(dst + (size_t)(start + 1) * EPS));
    issue_stage(wbase + STAGE_BYTES, h, sI1, dI1, lane);

    for (int s = 0; s < cnt; s++) {
        const bool more = (s + 2) < cnt;
        // prefetch idx two stages ahead (same/next 128B line: L1-hot)
        int4 sN, dN;
        if (more) {
            sN = __ldg((const int4*)(src + (size_t)(start + s + 2) * EPS));
            dN = __ldg((const int4*)(dst + (size_t)(start + s + 2) * EPS));
        }

        if (more) cp_wait1(); else cp_wait0();
        __syncwarp();

        const uint32_t buf = wbase + (uint32_t)(s & 1) * STAGE_BYTES;
        const int e0 = (start + s) * EPS;            // multiple of 4: no etype straddle
        const int t  = e0 / N_EDGES;
        const int rr = __ldg(&rel[t]);
        const float* wrow = W + rr * N_HID;

        // lane (o, j): accumulate edge o's partial over 4 chunks
        const uint32_t arow = buf + (uint32_t)(o * 2) * ROW_BYTES + j * 16;
        const uint32_t brow = arow + ROW_BYTES;

        float acc = 0.0f;
        #pragma unroll
        for (int c = 0; c < 4; c++) {
            float4 a, b;
            asm volatile("ld.shared.v4.f32 {%0,%1,%2,%3}, [%4];"
                         : "=f"(a.x), "=f"(a.y), "=f"(a.z), "=f"(a.w)
                         : "r"(arow + c * 128));
            asm volatile("ld.shared.v4.f32 {%0,%1,%2,%3}, [%4];"
                         : "=f"(b.x), "=f"(b.y), "=f"(b.z), "=f"(b.w)
                         : "r"(brow + c * 128));
            const float4 w = __ldg((const float4*)(wrow + c * 32) + j);
            acc = fmaf(a.x * w.x, b.x, acc);
            acc = fmaf(a.y * w.y, b.y, acc);
            acc = fmaf(a.z * w.z, b.z, acc);
            acc = fmaf(a.w * w.w, b.w, acc);
        }

        // reduce over the 8 lanes of the octet
        acc += __shfl_xor_sync(0xffffffffu, acc, 4);
        acc += __shfl_xor_sync(0xffffffffu, acc, 2);
        acc += __shfl_xor_sync(0xffffffffu, acc, 1);

        if (j == 0)
            out[e0 + o] = 1.0f / (1.0f + __expf(-acc));

        __syncwarp();        // all lanes done reading buf before refill
        if (more)
            issue_stage(buf, h, sN, dN, lane);
    }
}

extern "C" void kernel_launch(void* const* d_in, const int* in_sizes, int n_in,
                              void* d_out, int out_size)
{
    const float* h   = (const float*)d_in[0];   // [N_NODES, 128]
    const float* W   = (const float*)d_in[1];   // [10, 128]
    const int*   src = (const int*)d_in[2];     // [10, 100000] int32
    const int*   dst = (const int*)d_in[3];     // [10, 100000] int32
    const int*   rel = (const int*)d_in[4];     // [10] int32
    float* out = (float*)d_out;                 // [10, 100000]

    distmult_kernel<<<NBLOCKS, 128>>>(h, W, src, dst, rel, out);
}

// round 15
// speedup vs baseline: 1.5120x; 1.5120x over previous
#include <cuda_runtime.h>

#define N_HID     128
#define N_ETYPES  10
#define N_EDGES   100000
#define TOTAL_EDGES (N_ETYPES * N_EDGES)
#define EPW       4   // edges per warp (single group)

// Octet layout, single group: 8 lanes per edge (o = lane>>3), lane j = lane&7
// owns a 16B slice of each 128B chunk. 8 gathers in flight, minimal tail
// (16 FMA + 3 SHFL + store), low regs -> 10 blocks/SM (62.5% occ).
// Discriminates latency-bound vs L2-ceiling at the 54us plateau.
__global__ void __launch_bounds__(128, 10) distmult_kernel(
    const float* __restrict__ h,
    const float* __restrict__ W,
    const int* __restrict__ src,
    const int* __restrict__ dst,
    const int* __restrict__ rel,
    float* __restrict__ out)
{
    const int warp = (blockIdx.x * blockDim.x + threadIdx.x) >> 5;
    const int lane = threadIdx.x & 31;
    const int e0 = warp * EPW;
    if (e0 >= TOTAL_EDGES) return;

    const int j = lane & 7;        // 16B slice within chunk
    const int o = lane >> 3;       // edge within group

    const int t = e0 / N_EDGES;    // 100000 % 4 == 0: no etype straddle
    const int r = __ldg(&rel[t]);
    const float* wrow = W + r * N_HID;

    const int s = __ldg(src + e0 + o);
    const int d = __ldg(dst + e0 + o);
    const float* sa = h + (size_t)s * N_HID;
    const float* sb = h + (size_t)d * N_HID;

    // 8 independent gathers: 4 chunks x {src,dst}, all issued up front
    const float4 a0 = __ldg((const float4*)(sa +  0) + j);
    const float4 a1 = __ldg((const float4*)(sa + 32) + j);
    const float4 a2 = __ldg((const float4*)(sa + 64) + j);
    const float4 a3 = __ldg((const float4*)(sa + 96) + j);
    const float4 b0 = __ldg((const float4*)(sb +  0) + j);
    const float4 b1 = __ldg((const float4*)(sb + 32) + j);
    const float4 b2 = __ldg((const float4*)(sb + 64) + j);
    const float4 b3 = __ldg((const float4*)(sb + 96) + j);

    // W chunks loaded at consume time (L1-hot: 5KB table), 2 indep chains
    const float4 w0 = __ldg((const float4*)(wrow +  0) + j);
    float p0 = a0.x * w0.x * b0.x;
    p0 = fmaf(a0.y * w0.y, b0.y, p0);
    p0 = fmaf(a0.z * w0.z, b0.z, p0);
    p0 = fmaf(a0.w * w0.w, b0.w, p0);
    const float4 w1 = __ldg((const float4*)(wrow + 32) + j);
    float p1 = a1.x * w1.x * b1.x;
    p1 = fmaf(a1.y * w1.y, b1.y, p1);
    p1 = fmaf(a1.z * w1.z, b1.z, p1);
    p1 = fmaf(a1.w * w1.w, b1.w, p1);
    const float4 w2 = __ldg((const float4*)(wrow + 64) + j);
    p0 = fmaf(a2.x * w2.x, b2.x, p0);
    p0 = fmaf(a2.y * w2.y, b2.y, p0);
    p0 = fmaf(a2.z * w2.z, b2.z, p0);
    p0 = fmaf(a2.w * w2.w, b2.w, p0);
    const float4 w3 = __ldg((const float4*)(wrow + 96) + j);
    p1 = fmaf(a3.x * w3.x, b3.x, p1);
    p1 = fmaf(a3.y * w3.y, b3.y, p1);
    p1 = fmaf(a3.z * w3.z, b3.z, p1);
    p1 = fmaf(a3.w * w3.w, b3.w, p1);

    float acc = p0 + p1;

    // reduce over the 8 lanes of the octet: 3 SHFL
    acc += __shfl_xor_sync(0xffffffffu, acc, 4);
    acc += __shfl_xor_sync(0xffffffffu, acc, 2);
    acc += __shfl_xor_sync(0xffffffffu, acc, 1);

    if (j == 0)
        out[e0 + o] = 1.0f / (1.0f + __expf(-acc));   // 4 consecutive floats
}

extern "C" void kernel_launch(void* const* d_in, const int* in_sizes, int n_in,
                              void* d_out, int out_size)
{
    const float* h   = (const float*)d_in[0];   // [N_NODES, 128]
    const float* W   = (const float*)d_in[1];   // [10, 128]
    const int*   src = (const int*)d_in[2];     // [10, 100000] int32
    const int*   dst = (const int*)d_in[3];     // [10, 100000] int32
    const int*   rel = (const int*)d_in[4];     // [10] int32
    float* out = (float*)d_out;                 // [10, 100000]

    const int threads = 128;                     // 4 warps/block, 16 edges/block
    const int warps_needed = TOTAL_EDGES / EPW;  // 250000
    const int blocks = (warps_needed * 32 + threads - 1) / threads;  // 62500
    distmult_kernel<<<blocks, threads>>>(h, W, src, dst, rel, out);
}

// round 16
// speedup vs baseline: 1.6398x; 1.0845x over previous
#include <cuda_runtime.h>

#define N_HID     128
#define N_ETYPES  10
#define N_EDGES   100000
#define TOTAL_EDGES (N_ETYPES * N_EDGES)
#define EPW       8   // edges per warp (2 groups of 4)

// Octet layout (R11 base): 8 lanes per edge; j=lane&7 owns a 16B slice of each
// 128B chunk, o=lane>>3 owns the edge. h gathers use ld.global.nc with
// L1::no_allocate: every gathered line is fully consumed by its own load
// instruction (random indices, no reuse), so L1 allocation is pure overhead.
__device__ __forceinline__ float4 ldna(const float4* p) {
    float4 v;
    asm volatile("ld.global.nc.L1::no_allocate.v4.f32 {%0,%1,%2,%3}, [%4];"
                 : "=f"(v.x), "=f"(v.y), "=f"(v.z), "=f"(v.w) : "l"(p));
    return v;
}

__global__ void __launch_bounds__(128, 9) distmult_kernel(
    const float* __restrict__ h,
    const float* __restrict__ W,
    const int* __restrict__ src,
    const int* __restrict__ dst,
    const int* __restrict__ rel,
    float* __restrict__ out)
{
    const int warp = (blockIdx.x * blockDim.x + threadIdx.x) >> 5;
    const int lane = threadIdx.x & 31;
    const int e0 = warp * EPW;
    if (e0 >= TOTAL_EDGES) return;

    const int j = lane & 7;        // 16B slice within chunk
    const int o = lane >> 3;       // edge within group

    const int t = e0 / N_EDGES;    // 100000 % 8 == 0: no etype straddle
    const int r = __ldg(&rel[t]);
    const float* wrow = W + r * N_HID;

    float acc0, acc1;

#define GROUP(accv, gbase)                                                     \
    {                                                                          \
        const int s = __ldg(src + (gbase) + o);                                \
        const int d = __ldg(dst + (gbase) + o);                                \
        const float* sa = h + (size_t)s * N_HID;                               \
        const float* sb = h + (size_t)d * N_HID;                               \
        /* 8 independent no-allocate gathers: 4 chunks x {src,dst} */          \
        const float4 a0 = ldna((const float4*)(sa +  0) + j);                  \
        const float4 a1 = ldna((const float4*)(sa + 32) + j);                  \
        const float4 a2 = ldna((const float4*)(sa + 64) + j);                  \
        const float4 a3 = ldna((const float4*)(sa + 96) + j);                  \
        const float4 b0 = ldna((const float4*)(sb +  0) + j);                  \
        const float4 b1 = ldna((const float4*)(sb + 32) + j);                  \
        const float4 b2 = ldna((const float4*)(sb + 64) + j);                  \
        const float4 b3 = ldna((const float4*)(sb + 96) + j);                  \
        const float4 w0 = __ldg((const float4*)(wrow +  0) + j);               \
        const float4 w1 = __ldg((const float4*)(wrow + 32) + j);               \
        const float4 w2 = __ldg((const float4*)(wrow + 64) + j);               \
        const float4 w3 = __ldg((const float4*)(wrow + 96) + j);               \
        float p0 = a0.x * w0.x * b0.x;                                         \
        p0 = fmaf(a0.y * w0.y, b0.y, p0);                                      \
        p0 = fmaf(a0.z * w0.z, b0.z, p0);                                      \
        p0 = fmaf(a0.w * w0.w, b0.w, p0);                                      \
        float p1 = a1.x * w1.x * b1.x;                                         \
        p1 = fmaf(a1.y * w1.y, b1.y, p1);                                      \
        p1 = fmaf(a1.z * w1.z, b1.z, p1);                                      \
        p1 = fmaf(a1.w * w1.w, b1.w, p1);                                      \
        float p2 = a2.x * w2.x * b2.x;                                         \
        p2 = fmaf(a2.y * w2.y, b2.y, p2);                                      \
        p2 = fmaf(a2.z * w2.z, b2.z, p2);                                      \
        p2 = fmaf(a2.w * w2.w, b2.w, p2);                                      \
        float p3 = a3.x * w3.x * b3.x;                                         \
        p3 = fmaf(a3.y * w3.y, b3.y, p3);                                      \
        p3 = fmaf(a3.z * w3.z, b3.z, p3);                                      \
        p3 = fmaf(a3.w * w3.w, b3.w, p3);                                      \
        accv = (p0 + p1) + (p2 + p3);                                          \
    }

    GROUP(acc0, e0)        // edges e0   .. e0+3  (octet o -> edge e0+o)
    GROUP(acc1, e0 + 4)    // edges e0+4 .. e0+7
#undef GROUP

    // Reduce within octet (8 lanes) for both groups: 4 SHFL + 1 mux.
    acc0 += __shfl_xor_sync(0xffffffffu, acc0, 4);
    acc1 += __shfl_xor_sync(0xffffffffu, acc1, 4);
    float m = (lane & 4) ? acc1 : acc0;    // bit2 selects group
    m += __shfl_xor_sync(0xffffffffu, m, 2);
    m += __shfl_xor_sync(0xffffffffu, m, 1);
    // lane l: octet o = l>>3 , group g = (l>>2)&1 -> edge e0 + 4g + o

    if ((lane & 3) == 0) {
        const int g = (lane >> 2) & 1;
        const float sig = 1.0f / (1.0f + __expf(-m));
        out[e0 + 4 * g + o] = sig;   // 8 floats within one 32B span
    }
}

extern "C" void kernel_launch(void* const* d_in, const int* in_sizes, int n_in,
                              void* d_out, int out_size)
{
    const float* h   = (const float*)d_in[0];   // [N_NODES, 128]
    const float* W   = (const float*)d_in[1];   // [10, 128]
    const int*   src = (const int*)d_in[2];     // [10, 100000] int32
    const int*   dst = (const int*)d_in[3];     // [10, 100000] int32
    const int*   rel = (const int*)d_in[4];     // [10] int32
    float* out = (float*)d_out;                 // [10, 100000]

    const int threads = 128;                     // 4 warps/block, 32 edges/block
    const int warps_needed = TOTAL_EDGES / EPW;  // 125000
    const int blocks = (warps_needed * 32 + threads - 1) / threads;  // 31250
    distmult_kernel<<<blocks, threads>>>(h, W, src, dst, rel, out);
}

// round 17
// speedup vs baseline: 1.7216x; 1.0498x over previous
#include <cuda_runtime.h>

#define N_HID     128
#define N_ETYPES  10
#define N_EDGES   100000
#define TOTAL_EDGES (N_ETYPES * N_EDGES)
#define EPW       8   // edges per warp (2 groups of 4)

// Final kernel (R11 champion + sigmoid under store predicate).
// Octet layout: 8 lanes per edge. o = lane>>3 selects the edge within a group
// of 4; j = lane&7 selects a 16B slice of each 128B chunk (4 chunks per row).
// Each lane accumulates its edge's partial dot in ONE register across chunks:
// a warp needs only 2 accumulators for 8 edges; reduction = 4 SHFL + 1 mux.
// Per load instruction: 4 rows x 128B = 4 full cache lines (optimal).
// Measured wall: L2 random-gather delivery ~74% of peak; all structural
// variants (EPW 4/8/16, 32-lane vs octet, cp.async, L1 bypass) converge here.
__global__ void __launch_bounds__(128, 9) distmult_kernel(
    const float* __restrict__ h,
    const float* __restrict__ W,
    const int* __restrict__ src,
    const int* __restrict__ dst,
    const int* __restrict__ rel,
    float* __restrict__ out)
{
    const int warp = (blockIdx.x * blockDim.x + threadIdx.x) >> 5;
    const int lane = threadIdx.x & 31;
    const int e0 = warp * EPW;
    if (e0 >= TOTAL_EDGES) return;

    const int j = lane & 7;        // 16B slice within chunk
    const int o = lane >> 3;       // edge within group

    const int t = e0 / N_EDGES;    // 100000 % 8 == 0: no etype straddle
    const int r = __ldg(&rel[t]);
    const float* wrow = W + r * N_HID;

    float acc0, acc1;

#define GROUP(accv, gbase)                                                     \
    {                                                                          \
        const int s = __ldg(src + (gbase) + o);                                \
        const int d = __ldg(dst + (gbase) + o);                                \
        const float* sa = h + (size_t)s * N_HID;                               \
        const float* sb = h + (size_t)d * N_HID;                               \
        /* 8 independent gathers: 4 chunks x {src,dst} */                      \
        const float4 a0 = __ldg((const float4*)(sa +  0) + j);                 \
        const float4 a1 = __ldg((const float4*)(sa + 32) + j);                 \
        const float4 a2 = __ldg((const float4*)(sa + 64) + j);                 \
        const float4 a3 = __ldg((const float4*)(sa + 96) + j);                 \
        const float4 b0 = __ldg((const float4*)(sb +  0) + j);                 \
        const float4 b1 = __ldg((const float4*)(sb + 32) + j);                 \
        const float4 b2 = __ldg((const float4*)(sb + 64) + j);                 \
        const float4 b3 = __ldg((const float4*)(sb + 96) + j);                 \
        const float4 w0 = __ldg((const float4*)(wrow +  0) + j);               \
        const float4 w1 = __ldg((const float4*)(wrow + 32) + j);               \
        const float4 w2 = __ldg((const float4*)(wrow + 64) + j);               \
        const float4 w3 = __ldg((const float4*)(wrow + 96) + j);               \
        float x = a0.x * w0.x * b0.x;                                          \
        x = fmaf(a0.y * w0.y, b0.y, x);                                        \
        x = fmaf(a0.z * w0.z, b0.z, x);                                        \
        x = fmaf(a0.w * w0.w, b0.w, x);                                        \
        x = fmaf(a1.x * w1.x, b1.x, x);                                        \
        x = fmaf(a1.y * w1.y, b1.y, x);                                        \
        x = fmaf(a1.z * w1.z, b1.z, x);                                        \
        x = fmaf(a1.w * w1.w, b1.w, x);                                        \
        x = fmaf(a2.x * w2.x, b2.x, x);                                        \
        x = fmaf(a2.y * w2.y, b2.y, x);                                        \
        x = fmaf(a2.z * w2.z, b2.z, x);                                        \
        x = fmaf(a2.w * w2.w, b2.w, x);                                        \
        x = fmaf(a3.x * w3.x, b3.x, x);                                        \
        x = fmaf(a3.y * w3.y, b3.y, x);                                        \
        x = fmaf(a3.z * w3.z, b3.z, x);                                        \
        accv = fmaf(a3.w * w3.w, b3.w, x);                                     \
    }

    GROUP(acc0, e0)        // edges e0   .. e0+3  (octet o -> edge e0+o)
    GROUP(acc1, e0 + 4)    // edges e0+4 .. e0+7
#undef GROUP

    // Reduce within octet (8 lanes) for both groups: 4 SHFL + 1 mux.
    acc0 += __shfl_xor_sync(0xffffffffu, acc0, 4);
    acc1 += __shfl_xor_sync(0xffffffffu, acc1, 4);
    float m = (lane & 4) ? acc1 : acc0;    // bit2 selects group
    m += __shfl_xor_sync(0xffffffffu, m, 2);
    m += __shfl_xor_sync(0xffffffffu, m, 1);
    // lane l: octet o = l>>3 , group g = (l>>2)&1 -> edge e0 + 4g + o

    if ((lane & 3) == 0) {
        const int g = (lane >> 2) & 1;
        const float sig = 1.0f / (1.0f + __expf(-m));   // MUFU only on 8 storing lanes
        out[e0 + 4 * g + o] = sig;   // 8 floats within one 32B span
    }
}

extern "C" void kernel_launch(void* const* d_in, const int* in_sizes, int n_in,
                              void* d_out, int out_size)
{
    const float* h   = (const float*)d_in[0];   // [N_NODES, 128]
    const float* W   = (const float*)d_in[1];   // [10, 128]
    const int*   src = (const int*)d_in[2];     // [10, 100000] int32
    const int*   dst = (const int*)d_in[3];     // [10, 100000] int32
    const int*   rel = (const int*)d_in[4];     // [10] int32
    float* out = (float*)d_out;                 // [10, 100000]

    const int threads = 128;                     // 4 warps/block, 32 edges/block
    const int warps_needed = TOTAL_EDGES / EPW;  // 125000
    const int blocks = (warps_needed * 32 + threads - 1) / threads;  // 31250
    distmult_kernel<<<blocks, threads>>>(h, W, src, dst, rel, out);
}